// round 10
// baseline (speedup 1.0000x reference)
#include <cuda_runtime.h>
#include <cuda_fp16.h>
#include <cstdint>

// ---------------------------------------------------------------------------
// RecurrentGCN (GConvGRU single step, h0 = 0) on GB300 (sm_103 PTX target,
// no tcgen05 -> mma.sync HMMA fp16 path).
//
// Math (exact given h0 == 0):
//   norm[e] = -rsqrt(deg[row]) * w[e] * rsqrt(deg[col])
//   tx1 = prop(x); tx2 = 2*prop(tx1) - x
//   y[50000,128] = [x|tx1|tx2] @ Wbig[192,128]  (cols 0-63 z, 64-127 h)
//   z = sigmoid(y_z+bz); ht = tanh(y_h+bh); t = tanh((1-z)*ht)
//   out = sigmoid(t @ Wlin + blin)
// Numerics: A and W both plain fp16 (no split); y error ~2.4e-4 elementwise,
// measured-style rel_err ~1.2e-4 << 1e-3.
// ---------------------------------------------------------------------------

namespace {
constexpr int NN = 50000;
constexpr int EE = 800000;
constexpr int EBLK = (EE + 255) / 256;          // 3125
constexpr int XBLK = (NN * 32 + 255) / 256;     // 6250
constexpr int WBLK = (192 * 128) / 256;         // 96
}

__device__ float g_deg[NN];
__device__ int   g_cnt[NN];
__device__ int   g_offs[NN + 1];
__device__ int   g_wpos[NN];
__device__ uint2 g_edge[EE];                    // {src, bits(nrm)}
// fp16 feature sections: 0 = x, 1 = tx1, 2 = tx2; [sec][node][64]
__device__ __align__(16) __half g_Ahi[3 * NN * 64];
// pre-swizzled fp16 W chunks (one per Chebyshev order), 16KB each
__device__ __align__(16) unsigned char g_Bpack[3 * 16384];
__device__ float g_bcomb[128];

// ---------------- helpers --------------------------------------------------
__device__ __forceinline__ uint32_t smem_to_u32(const void* p) {
  uint32_t a;
  asm("{ .reg .u64 t; cvta.to.shared.u64 t, %1; cvt.u32.u64 %0, t; }"
      : "=r"(a) : "l"(p));
  return a;
}
__device__ __forceinline__ float tanh_fast(float v) {
  float r;
  asm("tanh.approx.f32 %0, %1;" : "=f"(r) : "f"(v));
  return r;
}
__device__ __forceinline__ float sigmoid_fast(float v) {
  return 0.5f * tanh_fast(0.5f * v) + 0.5f;
}
__device__ __forceinline__ void ldsm_x4(uint32_t* r, uint32_t addr) {
  asm volatile("ldmatrix.sync.aligned.m8n8.x4.shared.b16 {%0,%1,%2,%3}, [%4];"
               : "=r"(r[0]), "=r"(r[1]), "=r"(r[2]), "=r"(r[3]) : "r"(addr));
}
__device__ __forceinline__ void mma_fp16(float* d, const uint32_t* a,
                                         const uint32_t* b) {
  asm volatile(
      "mma.sync.aligned.m16n8k16.row.col.f32.f16.f16.f32 "
      "{%0,%1,%2,%3}, {%4,%5,%6,%7}, {%8,%9}, {%0,%1,%2,%3};"
      : "+f"(d[0]), "+f"(d[1]), "+f"(d[2]), "+f"(d[3])
      : "r"(a[0]), "r"(a[1]), "r"(a[2]), "r"(a[3]), "r"(b[0]), "r"(b[1]));
}
__device__ __forceinline__ void cp_async16(uint32_t dst, const void* src) {
  asm volatile("cp.async.cg.shared.global [%0], [%1], 16;"
               :: "r"(dst), "l"(src));
}
#define CP_COMMIT() asm volatile("cp.async.commit_group;" ::: "memory")
#define CP_WAIT(N) asm volatile("cp.async.wait_group %0;" :: "n"(N) : "memory")

// ---------------------------------------------------------------------------
// K1 (fused): edge accum | x -> fp16 | W pack (fp16, swizzled) | bias.
// Requires deg/cnt pre-zeroed (memset nodes in kernel_launch).
__global__ __launch_bounds__(256) void k_fused_init(
    const float* __restrict__ x, const int* __restrict__ ei,
    const float* __restrict__ w,
    const float* __restrict__ Wxz, const float* __restrict__ Wxh,
    const float* __restrict__ bxz, const float* __restrict__ bhz,
    const float* __restrict__ bxh, const float* __restrict__ bhh) {
  int b = blockIdx.x, tid = threadIdx.x;
  if (b < EBLK) {
    int e = b * 256 + tid;
    if (e < EE) {
      atomicAdd(&g_deg[ei[e]], w[e]);
      atomicAdd(&g_cnt[ei[EE + e]], 1);
    }
  } else if (b < EBLK + XBLK) {
    int idx = (b - EBLK) * 256 + tid;   // < NN*32
    float2 v = reinterpret_cast<const float2*>(x)[idx];
    reinterpret_cast<__half2*>(g_Ahi)[idx] = __float22half2_rn(v);
  } else if (b < EBLK + XBLK + WBLK) {
    int idx = (b - EBLK - XBLK) * 256 + tid;  // < 24576
    int kg = idx >> 7;                  // global k 0..191
    int n = idx & 127;
    int cheb = kg >> 6, kl = kg & 63;
    float wv = (n < 64) ? Wxz[cheb * 4096 + kl * 64 + n]
                        : Wxh[cheb * 4096 + kl * 64 + (n - 64)];
    uint32_t off = (uint32_t)n * 128 + ((((kl >> 3) ^ (n & 7)) << 4)) + (kl & 7) * 2;
    *(__half*)(g_Bpack + cheb * 16384 + off) = __float2half_rn(wv);
  } else {
    if (tid < 128)
      g_bcomb[tid] = (tid < 64) ? (bxz[tid] + bhz[tid])
                                : (bxh[tid - 64] + bhh[tid - 64]);
  }
}

// ---------------------------------------------------------------------------
// K2: single-block exclusive scan of cnt -> offs/wpos
__device__ __forceinline__ int warp_incl_scan(int v, int lane) {
#pragma unroll
  for (int d = 1; d < 32; d <<= 1) {
    int t = __shfl_up_sync(0xFFFFFFFFu, v, d);
    if (lane >= d) v += t;
  }
  return v;
}

__global__ __launch_bounds__(1024) void k_scan() {
  constexpr int T = 1024, IPT = 16, CH = T * IPT;
  __shared__ int wsum[32];
  __shared__ int carry_s;
  int tid = threadIdx.x, lane = tid & 31, wid = tid >> 5;
  if (tid == 0) carry_s = 0;
  __syncthreads();
  int nCh = (NN + CH - 1) / CH;
  for (int ch = 0; ch < nCh; ch++) {
    int base = ch * CH + tid * IPT;
    int v[IPT];
#pragma unroll
    for (int j = 0; j < IPT; j++) {
      int i = base + j;
      v[j] = (i < NN) ? g_cnt[i] : 0;
    }
    int tsum = 0;
#pragma unroll
    for (int j = 0; j < IPT; j++) tsum += v[j];
    int incl = warp_incl_scan(tsum, lane);
    if (lane == 31) wsum[wid] = incl;
    __syncthreads();
    if (wid == 0) {
      int wv = wsum[lane];
      int wincl = warp_incl_scan(wv, lane);
      wsum[lane] = wincl - wv;
    }
    __syncthreads();
    int run = carry_s + wsum[wid] + (incl - tsum);
#pragma unroll
    for (int j = 0; j < IPT; j++) {
      int i = base + j;
      if (i < NN) { g_offs[i] = run; g_wpos[i] = run; }
      run += v[j];
    }
    __syncthreads();
    if (tid == T - 1) carry_s = run;
    __syncthreads();
  }
  if (tid == 0) g_offs[NN] = carry_s;
}

// K3: norm (rsqrt inline) + CSR scatter, fused {src,nrm} 8B store
__global__ void k_edge_fill(const int* __restrict__ ei, const float* __restrict__ w) {
  int e = blockIdx.x * blockDim.x + threadIdx.x;
  if (e >= EE) return;
  int r = ei[e], c = ei[EE + e];
  float dr = g_deg[r], dc = g_deg[c];
  float ir = (dr > 0.0f) ? rsqrtf(dr) : 0.0f;
  float ic = (dc > 0.0f) ? rsqrtf(dc) : 0.0f;
  float nrm = -ir * w[e] * ic;
  int p = atomicAdd(&g_wpos[c], 1);
  g_edge[p] = make_uint2((uint32_t)r, __float_as_uint(nrm));
}

// K4/K5: warp-per-node CSR gather over fp16 rows (128B/row), MLP 16
__device__ __forceinline__ void prop_body(const __half2* __restrict__ vf,
                                          int s, int e, int lane,
                                          float& ax, float& ay) {
  int j = s;
  for (; j + 16 <= e; j += 16) {
    uint2 ed[16];
#pragma unroll
    for (int q = 0; q < 16; q++) ed[q] = g_edge[j + q];
    __half2 v[16];
#pragma unroll
    for (int q = 0; q < 16; q++) v[q] = vf[ed[q].x * 32 + lane];
#pragma unroll
    for (int q = 0; q < 16; q++) {
      float n = __uint_as_float(ed[q].y);
      float2 f = __half22float2(v[q]);
      ax += n * f.x; ay += n * f.y;
    }
  }
  if (j + 8 <= e) {
    uint2 ed[8];
#pragma unroll
    for (int q = 0; q < 8; q++) ed[q] = g_edge[j + q];
    __half2 v[8];
#pragma unroll
    for (int q = 0; q < 8; q++) v[q] = vf[ed[q].x * 32 + lane];
#pragma unroll
    for (int q = 0; q < 8; q++) {
      float n = __uint_as_float(ed[q].y);
      float2 f = __half22float2(v[q]);
      ax += n * f.x; ay += n * f.y;
    }
    j += 8;
  }
  if (j + 4 <= e) {
    uint2 ed[4];
#pragma unroll
    for (int q = 0; q < 4; q++) ed[q] = g_edge[j + q];
    __half2 v[4];
#pragma unroll
    for (int q = 0; q < 4; q++) v[q] = vf[ed[q].x * 32 + lane];
#pragma unroll
    for (int q = 0; q < 4; q++) {
      float n = __uint_as_float(ed[q].y);
      float2 f = __half22float2(v[q]);
      ax += n * f.x; ay += n * f.y;
    }
    j += 4;
  }
  for (; j < e; j++) {
    uint2 ed = g_edge[j];
    float2 f = __half22float2(vf[ed.x * 32 + lane]);
    float n = __uint_as_float(ed.y);
    ax += n * f.x; ay += n * f.y;
  }
}

__global__ __launch_bounds__(256) void k_prop1() {
  int gw = (blockIdx.x * blockDim.x + threadIdx.x) >> 5;
  int lane = threadIdx.x & 31;
  if (gw >= NN) return;
  int s = g_offs[gw], e = g_offs[gw + 1];
  float ax = 0.f, ay = 0.f;
  prop_body(reinterpret_cast<const __half2*>(g_Ahi), s, e, lane, ax, ay);
  reinterpret_cast<__half2*>(g_Ahi + (size_t)NN * 64)[gw * 32 + lane] =
      __float22half2_rn(make_float2(ax, ay));
}

__global__ __launch_bounds__(256) void k_prop2(const float* __restrict__ x) {
  int gw = (blockIdx.x * blockDim.x + threadIdx.x) >> 5;
  int lane = threadIdx.x & 31;
  if (gw >= NN) return;
  int s = g_offs[gw], e = g_offs[gw + 1];
  float ax = 0.f, ay = 0.f;
  prop_body(reinterpret_cast<const __half2*>(g_Ahi + (size_t)NN * 64),
            s, e, lane, ax, ay);
  float2 xv = reinterpret_cast<const float2*>(x)[gw * 32 + lane];
  reinterpret_cast<__half2*>(g_Ahi + (size_t)2 * NN * 64)[gw * 32 + lane] =
      __float22half2_rn(make_float2(2.0f * ax - xv.x, 2.0f * ay - xv.y));
}

// ---------------------------------------------------------------------------
// K6: mma.sync fp16 GEMM (128m x 128n, K = 3x64) + gates + head.
// SMEM: A [0,16K) | B [16K,64K): 3 chunks via cp.async.
// Epilogue overlays Y[128][130] fp32 at base, P partials at 66560.
static constexpr uint32_t A_OFF = 0;
static constexpr uint32_t B_OFF = 16384;
static constexpr uint32_t P_OFF = 66560;
static constexpr uint32_t SMEM_GEMM = 67584;

extern __shared__ char smem_dyn[];

__global__ __launch_bounds__(256, 2) void k_gemm(const float* __restrict__ Wlin,
                                                 const float* __restrict__ blin,
                                                 float* __restrict__ out) {
  char* smem = smem_dyn;
  uint32_t sA = smem_to_u32(smem) + A_OFF;
  uint32_t sB = smem_to_u32(smem) + B_OFF;
  int tid = threadIdx.x;
  int wid = tid >> 5, lane = tid & 31;
  int warpM = wid & 1, warpN = wid >> 1;
  int matq = lane >> 3, rq = lane & 7;

  float acc[4][4][4];
#pragma unroll
  for (int mi = 0; mi < 4; mi++)
#pragma unroll
    for (int j = 0; j < 4; j++)
#pragma unroll
      for (int q = 0; q < 4; q++) acc[mi][j][q] = 0.0f;

  int am = tid >> 1, ahalf = tid & 1;
  int node = blockIdx.x * 128 + am;
  if (node >= NN) node = NN - 1;

  // issue all 3 B chunk copies (in-order group commits)
#pragma unroll
  for (int i = 0; i < 3; i++) {
    const char* src = (const char*)g_Bpack + i * 16384 + tid * 16;
    uint32_t dst = sB + i * 16384 + tid * 16;
#pragma unroll
    for (int q = 0; q < 4; q++) cp_async16(dst + q * 4096, src + q * 4096);
    CP_COMMIT();
  }

#pragma unroll 1
  for (int s = 0; s < 3; s++) {
    // ---- stage A (LDG -> swizzled STS), 64B per thread ----
    const __half* asec = g_Ahi + (size_t)s * NN * 64 + (size_t)node * 64 + ahalf * 32;
    uint4 av[4];
#pragma unroll
    for (int g = 0; g < 4; g++)
      av[g] = *reinterpret_cast<const uint4*>(asec + g * 8);
    if (s > 0) __syncthreads();  // previous compute done before overwrite
#pragma unroll
    for (int g = 0; g < 4; g++) {
      int kg = ahalf * 4 + g;
      *reinterpret_cast<uint4*>(smem + A_OFF + am * 128 +
                                ((kg ^ (am & 7)) << 4)) = av[g];
    }
    if (s == 0) { CP_WAIT(2); }
    else if (s == 1) { CP_WAIT(1); }
    else { CP_WAIT(0); }
    __syncthreads();

    uint32_t sBc = sB + s * 16384;
    // ---- compute: 4 k16-steps ----
#pragma unroll
    for (int ks = 0; ks < 4; ks++) {
      uint32_t a[4][4], bb[4][2];
#pragma unroll
      for (int mi = 0; mi < 4; mi++) {
        int arow = warpM * 64 + mi * 16 + ((matq & 1) << 3) + rq;
        int k8 = ks * 2 + (matq >> 1);
        ldsm_x4(a[mi], sA + arow * 128 + ((k8 ^ (arow & 7)) << 4));
      }
#pragma unroll
      for (int jp = 0; jp < 2; jp++) {
        int nrow = warpN * 32 + jp * 16 + ((matq >> 1) << 3) + rq;
        int k8 = ks * 2 + (matq & 1);
        uint32_t t4[4];
        ldsm_x4(t4, sBc + nrow * 128 + ((k8 ^ (nrow & 7)) << 4));
        bb[jp * 2][0] = t4[0]; bb[jp * 2][1] = t4[1];
        bb[jp * 2 + 1][0] = t4[2]; bb[jp * 2 + 1][1] = t4[3];
      }
#pragma unroll
      for (int mi = 0; mi < 4; mi++)
#pragma unroll
        for (int j = 0; j < 4; j++) mma_fp16(acc[mi][j], a[mi], bb[j]);
    }
  }
  __syncthreads();

  // ---- write accumulators to smem Y[128][130] fp32 ----
  float* Y = reinterpret_cast<float*>(smem);
  {
    int gid = lane >> 2, tig = lane & 3;
#pragma unroll
    for (int mi = 0; mi < 4; mi++) {
      int row = warpM * 64 + mi * 16 + gid;
#pragma unroll
      for (int j = 0; j < 4; j++) {
        int col = warpN * 32 + j * 8 + tig * 2;
        Y[row * 130 + col] = acc[mi][j][0];
        Y[row * 130 + col + 1] = acc[mi][j][1];
        Y[(row + 8) * 130 + col] = acc[mi][j][2];
        Y[(row + 8) * 130 + col + 1] = acc[mi][j][3];
      }
    }
  }
  __syncthreads();

  // ---- gates + head ----
  {
    int half = tid >> 7, m = tid & 127;
    int cb = half * 32;
    float d0 = 0.f, d1 = 0.f;
#pragma unroll
    for (int q = 0; q < 32; q++) {
      int dim = cb + q;
      float z = sigmoid_fast(Y[m * 130 + dim] + g_bcomb[dim]);
      float ht = tanh_fast(Y[m * 130 + 64 + dim] + g_bcomb[64 + dim]);
      float t = tanh_fast((1.0f - z) * ht);
      d0 += t * Wlin[dim * 2];
      d1 += t * Wlin[dim * 2 + 1];
    }
    float2* P = reinterpret_cast<float2*>(smem + P_OFF);
    if (half) P[m] = make_float2(d0, d1);
    __syncthreads();
    if (!half) {
      int onode = blockIdx.x * 128 + m;
      if (onode < NN) {
        float2 p = P[m];
        float v0 = d0 + p.x + blin[0];
        float v1 = d1 + p.y + blin[1];
        float o0 = 1.0f / (1.0f + __expf(-v0));
        float o1 = 1.0f / (1.0f + __expf(-v1));
        *(float2*)(out + onode * 2) = make_float2(o0, o1);
      }
    }
  }
}

// ---------------------------------------------------------------------------
extern "C" void kernel_launch(void* const* d_in, const int* in_sizes, int n_in,
                              void* d_out, int out_size) {
  const float* x    = (const float*)d_in[0];
  const int*   ei   = (const int*)d_in[1];
  const float* w    = (const float*)d_in[2];
  const float* Wxz  = (const float*)d_in[3];
  const float* bxz  = (const float*)d_in[4];
  const float* bhz  = (const float*)d_in[6];
  const float* Wxh  = (const float*)d_in[11];
  const float* bxh  = (const float*)d_in[12];
  const float* bhh  = (const float*)d_in[14];
  const float* Wlin = (const float*)d_in[15];
  const float* blin = (const float*)d_in[16];
  float* out = (float*)d_out;

  cudaFuncSetAttribute(k_gemm, cudaFuncAttributeMaxDynamicSharedMemorySize,
                       SMEM_GEMM);

  void* p_deg = nullptr;
  void* p_cnt = nullptr;
  cudaGetSymbolAddress(&p_deg, g_deg);
  cudaGetSymbolAddress(&p_cnt, g_cnt);
  cudaMemsetAsync(p_deg, 0, NN * sizeof(float));
  cudaMemsetAsync(p_cnt, 0, NN * sizeof(int));

  k_fused_init<<<EBLK + XBLK + WBLK + 1, 256>>>(x, ei, w, Wxz, Wxh, bxz, bhz,
                                                bxh, bhh);
  k_scan<<<1, 1024>>>();
  k_edge_fill<<<(EE + 255) / 256, 256>>>(ei, w);
  k_prop1<<<(NN * 32 + 255) / 256, 256>>>();
  k_prop2<<<(NN * 32 + 255) / 256, 256>>>(x);
  k_gemm<<<(NN + 127) / 128, 256, SMEM_GEMM>>>(Wlin, blin, out);
}

// round 11
// speedup vs baseline: 1.4954x; 1.4954x over previous
#include <cuda_runtime.h>
#include <cuda_fp16.h>
#include <cstdint>

// ---------------------------------------------------------------------------
// RecurrentGCN (GConvGRU single step, h0 = 0) on GB300 (sm_103 PTX target,
// no tcgen05 -> mma.sync HMMA fp16 path).
//
// Math (exact given h0 == 0):
//   norm[e] = -rsqrt(deg[row]) * w[e] * rsqrt(deg[col])
//   tx1 = prop(x); tx2 = 2*prop(tx1) - x
//   y[50000,128] = [x|tx1|tx2] @ Wbig[192,128]  (cols 0-63 z, 64-127 h)
//   z = sigmoid(y_z+bz); ht = tanh(y_h+bh); t = tanh((1-z)*ht)
//   out = sigmoid(t @ Wlin + blin)
// Numerics: A and W in plain fp16 (measured rel_err ~6.6e-5 << 1e-3).
// Props: warp-per-node CSR gather, 8-deep load batching (MLP 8),
//        edge records store pre-scaled byte offsets {src*128, bits(nrm)}.
// ---------------------------------------------------------------------------

namespace {
constexpr int NN = 50000;
constexpr int EE = 800000;
constexpr int EBLK = (EE + 255) / 256;          // 3125
constexpr int XBLK = (NN * 32 + 255) / 256;     // 6250
constexpr int WBLK = (192 * 128) / 256;         // 96
}

__device__ float g_deg[NN];
__device__ int   g_cnt[NN];
__device__ int   g_offs[NN + 1];
__device__ int   g_wpos[NN];
__device__ uint2 g_edge[EE];                    // {src*128 (byte off), bits(nrm)}
// fp16 feature sections: 0 = x, 1 = tx1, 2 = tx2; [sec][node][64]
__device__ __align__(16) __half g_Ahi[3 * NN * 64];
// pre-swizzled fp16 W chunks (one per Chebyshev order), 16KB each
__device__ __align__(16) unsigned char g_Bpack[3 * 16384];
__device__ float g_bcomb[128];

// ---------------- helpers --------------------------------------------------
__device__ __forceinline__ uint32_t smem_to_u32(const void* p) {
  uint32_t a;
  asm("{ .reg .u64 t; cvta.to.shared.u64 t, %1; cvt.u32.u64 %0, t; }"
      : "=r"(a) : "l"(p));
  return a;
}
__device__ __forceinline__ float tanh_fast(float v) {
  float r;
  asm("tanh.approx.f32 %0, %1;" : "=f"(r) : "f"(v));
  return r;
}
__device__ __forceinline__ float sigmoid_fast(float v) {
  return 0.5f * tanh_fast(0.5f * v) + 0.5f;
}
__device__ __forceinline__ void ldsm_x4(uint32_t* r, uint32_t addr) {
  asm volatile("ldmatrix.sync.aligned.m8n8.x4.shared.b16 {%0,%1,%2,%3}, [%4];"
               : "=r"(r[0]), "=r"(r[1]), "=r"(r[2]), "=r"(r[3]) : "r"(addr));
}
__device__ __forceinline__ void mma_fp16(float* d, const uint32_t* a,
                                         const uint32_t* b) {
  asm volatile(
      "mma.sync.aligned.m16n8k16.row.col.f32.f16.f16.f32 "
      "{%0,%1,%2,%3}, {%4,%5,%6,%7}, {%8,%9}, {%0,%1,%2,%3};"
      : "+f"(d[0]), "+f"(d[1]), "+f"(d[2]), "+f"(d[3])
      : "r"(a[0]), "r"(a[1]), "r"(a[2]), "r"(a[3]), "r"(b[0]), "r"(b[1]));
}
__device__ __forceinline__ void cp_async16(uint32_t dst, const void* src) {
  asm volatile("cp.async.cg.shared.global [%0], [%1], 16;"
               :: "r"(dst), "l"(src));
}
#define CP_COMMIT() asm volatile("cp.async.commit_group;" ::: "memory")
#define CP_WAIT(N) asm volatile("cp.async.wait_group %0;" :: "n"(N) : "memory")

// ---------------------------------------------------------------------------
// K1 (fused): edge accum | x -> fp16 | W pack (fp16, swizzled) | bias.
// Requires deg/cnt pre-zeroed (memset nodes in kernel_launch).
__global__ __launch_bounds__(256) void k_fused_init(
    const float* __restrict__ x, const int* __restrict__ ei,
    const float* __restrict__ w,
    const float* __restrict__ Wxz, const float* __restrict__ Wxh,
    const float* __restrict__ bxz, const float* __restrict__ bhz,
    const float* __restrict__ bxh, const float* __restrict__ bhh) {
  int b = blockIdx.x, tid = threadIdx.x;
  if (b < EBLK) {
    int e = b * 256 + tid;
    if (e < EE) {
      atomicAdd(&g_deg[ei[e]], w[e]);
      atomicAdd(&g_cnt[ei[EE + e]], 1);
    }
  } else if (b < EBLK + XBLK) {
    int idx = (b - EBLK) * 256 + tid;   // < NN*32
    float2 v = reinterpret_cast<const float2*>(x)[idx];
    reinterpret_cast<__half2*>(g_Ahi)[idx] = __float22half2_rn(v);
  } else if (b < EBLK + XBLK + WBLK) {
    int idx = (b - EBLK - XBLK) * 256 + tid;  // < 24576
    int kg = idx >> 7;                  // global k 0..191
    int n = idx & 127;
    int cheb = kg >> 6, kl = kg & 63;
    float wv = (n < 64) ? Wxz[cheb * 4096 + kl * 64 + n]
                        : Wxh[cheb * 4096 + kl * 64 + (n - 64)];
    uint32_t off = (uint32_t)n * 128 + ((((kl >> 3) ^ (n & 7)) << 4)) + (kl & 7) * 2;
    *(__half*)(g_Bpack + cheb * 16384 + off) = __float2half_rn(wv);
  } else {
    if (tid < 128)
      g_bcomb[tid] = (tid < 64) ? (bxz[tid] + bhz[tid])
                                : (bxh[tid - 64] + bhh[tid - 64]);
  }
}

// ---------------------------------------------------------------------------
// K2: single-block exclusive scan of cnt -> offs/wpos
__device__ __forceinline__ int warp_incl_scan(int v, int lane) {
#pragma unroll
  for (int d = 1; d < 32; d <<= 1) {
    int t = __shfl_up_sync(0xFFFFFFFFu, v, d);
    if (lane >= d) v += t;
  }
  return v;
}

__global__ __launch_bounds__(1024) void k_scan() {
  constexpr int T = 1024, IPT = 16, CH = T * IPT;
  __shared__ int wsum[32];
  __shared__ int carry_s;
  int tid = threadIdx.x, lane = tid & 31, wid = tid >> 5;
  if (tid == 0) carry_s = 0;
  __syncthreads();
  int nCh = (NN + CH - 1) / CH;
  for (int ch = 0; ch < nCh; ch++) {
    int base = ch * CH + tid * IPT;
    int v[IPT];
#pragma unroll
    for (int j = 0; j < IPT; j++) {
      int i = base + j;
      v[j] = (i < NN) ? g_cnt[i] : 0;
    }
    int tsum = 0;
#pragma unroll
    for (int j = 0; j < IPT; j++) tsum += v[j];
    int incl = warp_incl_scan(tsum, lane);
    if (lane == 31) wsum[wid] = incl;
    __syncthreads();
    if (wid == 0) {
      int wv = wsum[lane];
      int wincl = warp_incl_scan(wv, lane);
      wsum[lane] = wincl - wv;
    }
    __syncthreads();
    int run = carry_s + wsum[wid] + (incl - tsum);
#pragma unroll
    for (int j = 0; j < IPT; j++) {
      int i = base + j;
      if (i < NN) { g_offs[i] = run; g_wpos[i] = run; }
      run += v[j];
    }
    __syncthreads();
    if (tid == T - 1) carry_s = run;
    __syncthreads();
  }
  if (tid == 0) g_offs[NN] = carry_s;
}

// K3: norm (rsqrt inline) + CSR scatter; src stored pre-scaled (bytes)
__global__ void k_edge_fill(const int* __restrict__ ei, const float* __restrict__ w) {
  int e = blockIdx.x * blockDim.x + threadIdx.x;
  if (e >= EE) return;
  int r = ei[e], c = ei[EE + e];
  float dr = g_deg[r], dc = g_deg[c];
  float ir = (dr > 0.0f) ? rsqrtf(dr) : 0.0f;
  float ic = (dc > 0.0f) ? rsqrtf(dc) : 0.0f;
  float nrm = -ir * w[e] * ic;
  int p = atomicAdd(&g_wpos[c], 1);
  g_edge[p] = make_uint2((uint32_t)r << 7, __float_as_uint(nrm));
}

// K4/K5: warp-per-node CSR gather over fp16 rows (128B/row), MLP 8
__device__ __forceinline__ void prop_body(const char* __restrict__ vbase,
                                          int s, int e, int lane4,
                                          float& ax, float& ay) {
  int j = s;
  for (; j + 8 <= e; j += 8) {
    uint2 ed[8];
#pragma unroll
    for (int q = 0; q < 8; q++) ed[q] = g_edge[j + q];
    __half2 v[8];
#pragma unroll
    for (int q = 0; q < 8; q++)
      v[q] = *reinterpret_cast<const __half2*>(vbase + ed[q].x + lane4);
#pragma unroll
    for (int q = 0; q < 8; q++) {
      float n = __uint_as_float(ed[q].y);
      float2 f = __half22float2(v[q]);
      ax += n * f.x; ay += n * f.y;
    }
  }
  if (j + 4 <= e) {
    uint2 ed[4];
#pragma unroll
    for (int q = 0; q < 4; q++) ed[q] = g_edge[j + q];
    __half2 v[4];
#pragma unroll
    for (int q = 0; q < 4; q++)
      v[q] = *reinterpret_cast<const __half2*>(vbase + ed[q].x + lane4);
#pragma unroll
    for (int q = 0; q < 4; q++) {
      float n = __uint_as_float(ed[q].y);
      float2 f = __half22float2(v[q]);
      ax += n * f.x; ay += n * f.y;
    }
    j += 4;
  }
  for (; j < e; j++) {
    uint2 ed = g_edge[j];
    float2 f = __half22float2(
        *reinterpret_cast<const __half2*>(vbase + ed.x + lane4));
    float n = __uint_as_float(ed.y);
    ax += n * f.x; ay += n * f.y;
  }
}

__global__ __launch_bounds__(256) void k_prop1() {
  int gw = (blockIdx.x * blockDim.x + threadIdx.x) >> 5;
  int lane = threadIdx.x & 31;
  if (gw >= NN) return;
  int s = g_offs[gw], e = g_offs[gw + 1];
  float ax = 0.f, ay = 0.f;
  prop_body(reinterpret_cast<const char*>(g_Ahi), s, e, lane * 4, ax, ay);
  reinterpret_cast<__half2*>(g_Ahi + (size_t)NN * 64)[gw * 32 + lane] =
      __float22half2_rn(make_float2(ax, ay));
}

__global__ __launch_bounds__(256) void k_prop2(const float* __restrict__ x) {
  int gw = (blockIdx.x * blockDim.x + threadIdx.x) >> 5;
  int lane = threadIdx.x & 31;
  if (gw >= NN) return;
  int s = g_offs[gw], e = g_offs[gw + 1];
  float ax = 0.f, ay = 0.f;
  prop_body(reinterpret_cast<const char*>(g_Ahi + (size_t)NN * 64), s, e,
            lane * 4, ax, ay);
  float2 xv = reinterpret_cast<const float2*>(x)[gw * 32 + lane];
  reinterpret_cast<__half2*>(g_Ahi + (size_t)2 * NN * 64)[gw * 32 + lane] =
      __float22half2_rn(make_float2(2.0f * ax - xv.x, 2.0f * ay - xv.y));
}

// ---------------------------------------------------------------------------
// K6: mma.sync fp16 GEMM (128m x 128n, K = 3x64) + gates + head.
// SMEM: A [0,16K) | B [16K,64K): 3 chunks via cp.async.
// Epilogue overlays Y[128][130] fp32 at base, P partials at 66560.
static constexpr uint32_t A_OFF = 0;
static constexpr uint32_t B_OFF = 16384;
static constexpr uint32_t P_OFF = 66560;
static constexpr uint32_t SMEM_GEMM = 67584;

extern __shared__ char smem_dyn[];

__global__ __launch_bounds__(256, 2) void k_gemm(const float* __restrict__ Wlin,
                                                 const float* __restrict__ blin,
                                                 float* __restrict__ out) {
  char* smem = smem_dyn;
  uint32_t sA = smem_to_u32(smem) + A_OFF;
  uint32_t sB = smem_to_u32(smem) + B_OFF;
  int tid = threadIdx.x;
  int wid = tid >> 5, lane = tid & 31;
  int warpM = wid & 1, warpN = wid >> 1;
  int matq = lane >> 3, rq = lane & 7;

  float acc[4][4][4];
#pragma unroll
  for (int mi = 0; mi < 4; mi++)
#pragma unroll
    for (int j = 0; j < 4; j++)
#pragma unroll
      for (int q = 0; q < 4; q++) acc[mi][j][q] = 0.0f;

  int am = tid >> 1, ahalf = tid & 1;
  int node = blockIdx.x * 128 + am;
  if (node >= NN) node = NN - 1;

  // issue all 3 B chunk copies (in-order group commits)
#pragma unroll
  for (int i = 0; i < 3; i++) {
    const char* src = (const char*)g_Bpack + i * 16384 + tid * 16;
    uint32_t dst = sB + i * 16384 + tid * 16;
#pragma unroll
    for (int q = 0; q < 4; q++) cp_async16(dst + q * 4096, src + q * 4096);
    CP_COMMIT();
  }

#pragma unroll 1
  for (int s = 0; s < 3; s++) {
    // ---- stage A (LDG -> swizzled STS), 64B per thread ----
    const __half* asec = g_Ahi + (size_t)s * NN * 64 + (size_t)node * 64 + ahalf * 32;
    uint4 av[4];
#pragma unroll
    for (int g = 0; g < 4; g++)
      av[g] = *reinterpret_cast<const uint4*>(asec + g * 8);
    if (s > 0) __syncthreads();  // previous compute done before overwrite
#pragma unroll
    for (int g = 0; g < 4; g++) {
      int kg = ahalf * 4 + g;
      *reinterpret_cast<uint4*>(smem + A_OFF + am * 128 +
                                ((kg ^ (am & 7)) << 4)) = av[g];
    }
    if (s == 0) { CP_WAIT(2); }
    else if (s == 1) { CP_WAIT(1); }
    else { CP_WAIT(0); }
    __syncthreads();

    uint32_t sBc = sB + s * 16384;
    // ---- compute: 4 k16-steps ----
#pragma unroll
    for (int ks = 0; ks < 4; ks++) {
      uint32_t a[4][4], bb[4][2];
#pragma unroll
      for (int mi = 0; mi < 4; mi++) {
        int arow = warpM * 64 + mi * 16 + ((matq & 1) << 3) + rq;
        int k8 = ks * 2 + (matq >> 1);
        ldsm_x4(a[mi], sA + arow * 128 + ((k8 ^ (arow & 7)) << 4));
      }
#pragma unroll
      for (int jp = 0; jp < 2; jp++) {
        int nrow = warpN * 32 + jp * 16 + ((matq >> 1) << 3) + rq;
        int k8 = ks * 2 + (matq & 1);
        uint32_t t4[4];
        ldsm_x4(t4, sBc + nrow * 128 + ((k8 ^ (nrow & 7)) << 4));
        bb[jp * 2][0] = t4[0]; bb[jp * 2][1] = t4[1];
        bb[jp * 2 + 1][0] = t4[2]; bb[jp * 2 + 1][1] = t4[3];
      }
#pragma unroll
      for (int mi = 0; mi < 4; mi++)
#pragma unroll
        for (int j = 0; j < 4; j++) mma_fp16(acc[mi][j], a[mi], bb[j]);
    }
  }
  __syncthreads();

  // ---- write accumulators to smem Y[128][130] fp32 ----
  float* Y = reinterpret_cast<float*>(smem);
  {
    int gid = lane >> 2, tig = lane & 3;
#pragma unroll
    for (int mi = 0; mi < 4; mi++) {
      int row = warpM * 64 + mi * 16 + gid;
#pragma unroll
      for (int j = 0; j < 4; j++) {
        int col = warpN * 32 + j * 8 + tig * 2;
        Y[row * 130 + col] = acc[mi][j][0];
        Y[row * 130 + col + 1] = acc[mi][j][1];
        Y[(row + 8) * 130 + col] = acc[mi][j][2];
        Y[(row + 8) * 130 + col + 1] = acc[mi][j][3];
      }
    }
  }
  __syncthreads();

  // ---- gates + head ----
  {
    int half = tid >> 7, m = tid & 127;
    int cb = half * 32;
    float d0 = 0.f, d1 = 0.f;
#pragma unroll
    for (int q = 0; q < 32; q++) {
      int dim = cb + q;
      float z = sigmoid_fast(Y[m * 130 + dim] + g_bcomb[dim]);
      float ht = tanh_fast(Y[m * 130 + 64 + dim] + g_bcomb[64 + dim]);
      float t = tanh_fast((1.0f - z) * ht);
      d0 += t * Wlin[dim * 2];
      d1 += t * Wlin[dim * 2 + 1];
    }
    float2* P = reinterpret_cast<float2*>(smem + P_OFF);
    if (half) P[m] = make_float2(d0, d1);
    __syncthreads();
    if (!half) {
      int onode = blockIdx.x * 128 + m;
      if (onode < NN) {
        float2 p = P[m];
        float v0 = d0 + p.x + blin[0];
        float v1 = d1 + p.y + blin[1];
        float o0 = 1.0f / (1.0f + __expf(-v0));
        float o1 = 1.0f / (1.0f + __expf(-v1));
        *(float2*)(out + onode * 2) = make_float2(o0, o1);
      }
    }
  }
}

// ---------------------------------------------------------------------------
extern "C" void kernel_launch(void* const* d_in, const int* in_sizes, int n_in,
                              void* d_out, int out_size) {
  const float* x    = (const float*)d_in[0];
  const int*   ei   = (const int*)d_in[1];
  const float* w    = (const float*)d_in[2];
  const float* Wxz  = (const float*)d_in[3];
  const float* bxz  = (const float*)d_in[4];
  const float* bhz  = (const float*)d_in[6];
  const float* Wxh  = (const float*)d_in[11];
  const float* bxh  = (const float*)d_in[12];
  const float* bhh  = (const float*)d_in[14];
  const float* Wlin = (const float*)d_in[15];
  const float* blin = (const float*)d_in[16];
  float* out = (float*)d_out;

  cudaFuncSetAttribute(k_gemm, cudaFuncAttributeMaxDynamicSharedMemorySize,
                       SMEM_GEMM);

  void* p_deg = nullptr;
  void* p_cnt = nullptr;
  cudaGetSymbolAddress(&p_deg, g_deg);
  cudaGetSymbolAddress(&p_cnt, g_cnt);
  cudaMemsetAsync(p_deg, 0, NN * sizeof(float));
  cudaMemsetAsync(p_cnt, 0, NN * sizeof(int));

  k_fused_init<<<EBLK + XBLK + WBLK + 1, 256>>>(x, ei, w, Wxz, Wxh, bxz, bhz,
                                                bxh, bhh);
  k_scan<<<1, 1024>>>();
  k_edge_fill<<<(EE + 255) / 256, 256>>>(ei, w);
  k_prop1<<<(NN * 32 + 255) / 256, 256>>>();
  k_prop2<<<(NN * 32 + 255) / 256, 256>>>(x);
  k_gemm<<<(NN + 127) / 128, 256, SMEM_GEMM>>>(Wlin, blin, out);
}

// round 12
// speedup vs baseline: 1.4960x; 1.0004x over previous
#include <cuda_runtime.h>
#include <cuda_fp16.h>
#include <cstdint>

// ---------------------------------------------------------------------------
// RecurrentGCN (GConvGRU single step, h0 = 0) on GB300 (sm_103 PTX target,
// no tcgen05 -> mma.sync HMMA fp16 path).
//
// Math (exact given h0 == 0):
//   norm[e] = -rsqrt(deg[row]) * w[e] * rsqrt(deg[col])
//   tx1 = prop(x); tx2 = 2*prop(tx1) - x
//   y[50000,128] = [x|tx1|tx2] @ Wbig[192,128]  (cols 0-63 z, 64-127 h)
//   z = sigmoid(y_z+bz); ht = tanh(y_h+bh); t = tanh((1-z)*ht)
//   out = sigmoid(t @ Wlin + blin)
// Numerics: A and W in plain fp16 (measured rel_err ~6.6e-5 << 1e-3).
// Props: 2-edges-per-warp CSR gather: half-warp per edge, lane owns 8B
//        (4 features) of the row; 8-deep batches = 16 edges in flight.
// ---------------------------------------------------------------------------

namespace {
constexpr int NN = 50000;
constexpr int EE = 800000;
constexpr int EBLK = (EE + 255) / 256;          // 3125
constexpr int XBLK = (NN * 32 + 255) / 256;     // 6250
constexpr int WBLK = (192 * 128) / 256;         // 96
}

__device__ float g_deg[NN];
__device__ int   g_cnt[NN];
__device__ int   g_offs[NN + 1];
__device__ int   g_wpos[NN];
__device__ uint2 g_edge[EE];                    // {src*128 (byte off), bits(nrm)}
// fp16 feature sections: 0 = x, 1 = tx1, 2 = tx2; [sec][node][64]
__device__ __align__(16) __half g_Ahi[3 * NN * 64];
// pre-swizzled fp16 W chunks (one per Chebyshev order), 16KB each
__device__ __align__(16) unsigned char g_Bpack[3 * 16384];
__device__ float g_bcomb[128];

// ---------------- helpers --------------------------------------------------
__device__ __forceinline__ uint32_t smem_to_u32(const void* p) {
  uint32_t a;
  asm("{ .reg .u64 t; cvta.to.shared.u64 t, %1; cvt.u32.u64 %0, t; }"
      : "=r"(a) : "l"(p));
  return a;
}
__device__ __forceinline__ float tanh_fast(float v) {
  float r;
  asm("tanh.approx.f32 %0, %1;" : "=f"(r) : "f"(v));
  return r;
}
__device__ __forceinline__ float sigmoid_fast(float v) {
  return 0.5f * tanh_fast(0.5f * v) + 0.5f;
}
__device__ __forceinline__ void ldsm_x4(uint32_t* r, uint32_t addr) {
  asm volatile("ldmatrix.sync.aligned.m8n8.x4.shared.b16 {%0,%1,%2,%3}, [%4];"
               : "=r"(r[0]), "=r"(r[1]), "=r"(r[2]), "=r"(r[3]) : "r"(addr));
}
__device__ __forceinline__ void mma_fp16(float* d, const uint32_t* a,
                                         const uint32_t* b) {
  asm volatile(
      "mma.sync.aligned.m16n8k16.row.col.f32.f16.f16.f32 "
      "{%0,%1,%2,%3}, {%4,%5,%6,%7}, {%8,%9}, {%0,%1,%2,%3};"
      : "+f"(d[0]), "+f"(d[1]), "+f"(d[2]), "+f"(d[3])
      : "r"(a[0]), "r"(a[1]), "r"(a[2]), "r"(a[3]), "r"(b[0]), "r"(b[1]));
}
__device__ __forceinline__ void cp_async16(uint32_t dst, const void* src) {
  asm volatile("cp.async.cg.shared.global [%0], [%1], 16;"
               :: "r"(dst), "l"(src));
}
#define CP_COMMIT() asm volatile("cp.async.commit_group;" ::: "memory")
#define CP_WAIT(N) asm volatile("cp.async.wait_group %0;" :: "n"(N) : "memory")

// ---------------------------------------------------------------------------
// K1 (fused): edge accum | x -> fp16 | W pack (fp16, swizzled) | bias.
// Requires deg/cnt pre-zeroed (memset nodes in kernel_launch).
__global__ __launch_bounds__(256) void k_fused_init(
    const float* __restrict__ x, const int* __restrict__ ei,
    const float* __restrict__ w,
    const float* __restrict__ Wxz, const float* __restrict__ Wxh,
    const float* __restrict__ bxz, const float* __restrict__ bhz,
    const float* __restrict__ bxh, const float* __restrict__ bhh) {
  int b = blockIdx.x, tid = threadIdx.x;
  if (b < EBLK) {
    int e = b * 256 + tid;
    if (e < EE) {
      atomicAdd(&g_deg[ei[e]], w[e]);
      atomicAdd(&g_cnt[ei[EE + e]], 1);
    }
  } else if (b < EBLK + XBLK) {
    int idx = (b - EBLK) * 256 + tid;   // < NN*32
    float2 v = reinterpret_cast<const float2*>(x)[idx];
    reinterpret_cast<__half2*>(g_Ahi)[idx] = __float22half2_rn(v);
  } else if (b < EBLK + XBLK + WBLK) {
    int idx = (b - EBLK - XBLK) * 256 + tid;  // < 24576
    int kg = idx >> 7;                  // global k 0..191
    int n = idx & 127;
    int cheb = kg >> 6, kl = kg & 63;
    float wv = (n < 64) ? Wxz[cheb * 4096 + kl * 64 + n]
                        : Wxh[cheb * 4096 + kl * 64 + (n - 64)];
    uint32_t off = (uint32_t)n * 128 + ((((kl >> 3) ^ (n & 7)) << 4)) + (kl & 7) * 2;
    *(__half*)(g_Bpack + cheb * 16384 + off) = __float2half_rn(wv);
  } else {
    if (tid < 128)
      g_bcomb[tid] = (tid < 64) ? (bxz[tid] + bhz[tid])
                                : (bxh[tid - 64] + bhh[tid - 64]);
  }
}

// ---------------------------------------------------------------------------
// K2: single-block exclusive scan of cnt -> offs/wpos
__device__ __forceinline__ int warp_incl_scan(int v, int lane) {
#pragma unroll
  for (int d = 1; d < 32; d <<= 1) {
    int t = __shfl_up_sync(0xFFFFFFFFu, v, d);
    if (lane >= d) v += t;
  }
  return v;
}

__global__ __launch_bounds__(1024) void k_scan() {
  constexpr int T = 1024, IPT = 16, CH = T * IPT;
  __shared__ int wsum[32];
  __shared__ int carry_s;
  int tid = threadIdx.x, lane = tid & 31, wid = tid >> 5;
  if (tid == 0) carry_s = 0;
  __syncthreads();
  int nCh = (NN + CH - 1) / CH;
  for (int ch = 0; ch < nCh; ch++) {
    int base = ch * CH + tid * IPT;
    int v[IPT];
#pragma unroll
    for (int j = 0; j < IPT; j++) {
      int i = base + j;
      v[j] = (i < NN) ? g_cnt[i] : 0;
    }
    int tsum = 0;
#pragma unroll
    for (int j = 0; j < IPT; j++) tsum += v[j];
    int incl = warp_incl_scan(tsum, lane);
    if (lane == 31) wsum[wid] = incl;
    __syncthreads();
    if (wid == 0) {
      int wv = wsum[lane];
      int wincl = warp_incl_scan(wv, lane);
      wsum[lane] = wincl - wv;
    }
    __syncthreads();
    int run = carry_s + wsum[wid] + (incl - tsum);
#pragma unroll
    for (int j = 0; j < IPT; j++) {
      int i = base + j;
      if (i < NN) { g_offs[i] = run; g_wpos[i] = run; }
      run += v[j];
    }
    __syncthreads();
    if (tid == T - 1) carry_s = run;
    __syncthreads();
  }
  if (tid == 0) g_offs[NN] = carry_s;
}

// K3: norm (rsqrt inline) + CSR scatter; src stored pre-scaled (bytes)
__global__ void k_edge_fill(const int* __restrict__ ei, const float* __restrict__ w) {
  int e = blockIdx.x * blockDim.x + threadIdx.x;
  if (e >= EE) return;
  int r = ei[e], c = ei[EE + e];
  float dr = g_deg[r], dc = g_deg[c];
  float ir = (dr > 0.0f) ? rsqrtf(dr) : 0.0f;
  float ic = (dc > 0.0f) ? rsqrtf(dc) : 0.0f;
  float nrm = -ir * w[e] * ic;
  int p = atomicAdd(&g_wpos[c], 1);
  g_edge[p] = make_uint2((uint32_t)r << 7, __float_as_uint(nrm));
}

// ---------------------------------------------------------------------------
// K4/K5: 2-edges-per-warp CSR gather. half = lane>>4 selects edge parity;
// lane owns 8B (features 4*hl .. 4*hl+3). 8-deep batch = 16 edges in flight.
__device__ __forceinline__ void edge_acc(const char* __restrict__ vbase,
                                         uint2 ed, int off8, float4& acc) {
  uint2 v = *reinterpret_cast<const uint2*>(vbase + ed.x + off8);
  float n = __uint_as_float(ed.y);
  float2 f0 = __half22float2(*reinterpret_cast<__half2*>(&v.x));
  float2 f1 = __half22float2(*reinterpret_cast<__half2*>(&v.y));
  acc.x += n * f0.x; acc.y += n * f0.y;
  acc.z += n * f1.x; acc.w += n * f1.y;
}

__device__ __forceinline__ void prop_body(const char* __restrict__ vbase,
                                          int s, int e, int half, int off8,
                                          float4& acc) {
  int j = s;
  for (; j + 16 <= e; j += 16) {
    uint2 ed[8];
#pragma unroll
    for (int q = 0; q < 8; q++) ed[q] = g_edge[j + 2 * q + half];
    uint2 v[8];
#pragma unroll
    for (int q = 0; q < 8; q++)
      v[q] = *reinterpret_cast<const uint2*>(vbase + ed[q].x + off8);
#pragma unroll
    for (int q = 0; q < 8; q++) {
      float n = __uint_as_float(ed[q].y);
      float2 f0 = __half22float2(*reinterpret_cast<__half2*>(&v[q].x));
      float2 f1 = __half22float2(*reinterpret_cast<__half2*>(&v[q].y));
      acc.x += n * f0.x; acc.y += n * f0.y;
      acc.z += n * f1.x; acc.w += n * f1.y;
    }
  }
  if (j + 8 <= e) {
    uint2 ed[4];
#pragma unroll
    for (int q = 0; q < 4; q++) ed[q] = g_edge[j + 2 * q + half];
    uint2 v[4];
#pragma unroll
    for (int q = 0; q < 4; q++)
      v[q] = *reinterpret_cast<const uint2*>(vbase + ed[q].x + off8);
#pragma unroll
    for (int q = 0; q < 4; q++) {
      float n = __uint_as_float(ed[q].y);
      float2 f0 = __half22float2(*reinterpret_cast<__half2*>(&v[q].x));
      float2 f1 = __half22float2(*reinterpret_cast<__half2*>(&v[q].y));
      acc.x += n * f0.x; acc.y += n * f0.y;
      acc.z += n * f1.x; acc.w += n * f1.y;
    }
    j += 8;
  }
  for (; j + 2 <= e; j += 2) edge_acc(vbase, g_edge[j + half], off8, acc);
  if (j < e && half == 0) edge_acc(vbase, g_edge[j], off8, acc);
}

__device__ __forceinline__ void merge_acc(float4& acc) {
  acc.x += __shfl_down_sync(0xFFFFFFFFu, acc.x, 16);
  acc.y += __shfl_down_sync(0xFFFFFFFFu, acc.y, 16);
  acc.z += __shfl_down_sync(0xFFFFFFFFu, acc.z, 16);
  acc.w += __shfl_down_sync(0xFFFFFFFFu, acc.w, 16);
}

__global__ __launch_bounds__(256) void k_prop1() {
  int gw = (blockIdx.x * blockDim.x + threadIdx.x) >> 5;
  int lane = threadIdx.x & 31;
  if (gw >= NN) return;
  int half = lane >> 4, hl = lane & 15;
  int s = g_offs[gw], e = g_offs[gw + 1];
  float4 acc = make_float4(0.f, 0.f, 0.f, 0.f);
  prop_body(reinterpret_cast<const char*>(g_Ahi), s, e, half, hl * 8, acc);
  merge_acc(acc);
  if (half == 0) {
    __half2 h0 = __float22half2_rn(make_float2(acc.x, acc.y));
    __half2 h1 = __float22half2_rn(make_float2(acc.z, acc.w));
    uint2 o;
    o.x = *reinterpret_cast<uint32_t*>(&h0);
    o.y = *reinterpret_cast<uint32_t*>(&h1);
    *reinterpret_cast<uint2*>(
        reinterpret_cast<char*>(g_Ahi + (size_t)NN * 64) + gw * 128 + hl * 8) = o;
  }
}

__global__ __launch_bounds__(256) void k_prop2(const float* __restrict__ x) {
  int gw = (blockIdx.x * blockDim.x + threadIdx.x) >> 5;
  int lane = threadIdx.x & 31;
  if (gw >= NN) return;
  int half = lane >> 4, hl = lane & 15;
  int s = g_offs[gw], e = g_offs[gw + 1];
  float4 acc = make_float4(0.f, 0.f, 0.f, 0.f);
  prop_body(reinterpret_cast<const char*>(g_Ahi + (size_t)NN * 64), s, e, half,
            hl * 8, acc);
  merge_acc(acc);
  if (half == 0) {
    float4 xv = *reinterpret_cast<const float4*>(x + (size_t)gw * 64 + hl * 4);
    __half2 h0 = __float22half2_rn(
        make_float2(2.0f * acc.x - xv.x, 2.0f * acc.y - xv.y));
    __half2 h1 = __float22half2_rn(
        make_float2(2.0f * acc.z - xv.z, 2.0f * acc.w - xv.w));
    uint2 o;
    o.x = *reinterpret_cast<uint32_t*>(&h0);
    o.y = *reinterpret_cast<uint32_t*>(&h1);
    *reinterpret_cast<uint2*>(
        reinterpret_cast<char*>(g_Ahi + (size_t)2 * NN * 64) + gw * 128 + hl * 8) = o;
  }
}

// ---------------------------------------------------------------------------
// K6: mma.sync fp16 GEMM (128m x 128n, K = 3x64) + gates + head.
// SMEM: A [0,16K) | B [16K,64K): 3 chunks via cp.async.
// Epilogue overlays Y[128][130] fp32 at base, P partials at 66560.
static constexpr uint32_t A_OFF = 0;
static constexpr uint32_t B_OFF = 16384;
static constexpr uint32_t P_OFF = 66560;
static constexpr uint32_t SMEM_GEMM = 67584;

extern __shared__ char smem_dyn[];

__global__ __launch_bounds__(256, 2) void k_gemm(const float* __restrict__ Wlin,
                                                 const float* __restrict__ blin,
                                                 float* __restrict__ out) {
  char* smem = smem_dyn;
  uint32_t sA = smem_to_u32(smem) + A_OFF;
  uint32_t sB = smem_to_u32(smem) + B_OFF;
  int tid = threadIdx.x;
  int wid = tid >> 5, lane = tid & 31;
  int warpM = wid & 1, warpN = wid >> 1;
  int matq = lane >> 3, rq = lane & 7;

  float acc[4][4][4];
#pragma unroll
  for (int mi = 0; mi < 4; mi++)
#pragma unroll
    for (int j = 0; j < 4; j++)
#pragma unroll
      for (int q = 0; q < 4; q++) acc[mi][j][q] = 0.0f;

  int am = tid >> 1, ahalf = tid & 1;
  int node = blockIdx.x * 128 + am;
  if (node >= NN) node = NN - 1;

  // issue all 3 B chunk copies (in-order group commits)
#pragma unroll
  for (int i = 0; i < 3; i++) {
    const char* src = (const char*)g_Bpack + i * 16384 + tid * 16;
    uint32_t dst = sB + i * 16384 + tid * 16;
#pragma unroll
    for (int q = 0; q < 4; q++) cp_async16(dst + q * 4096, src + q * 4096);
    CP_COMMIT();
  }

#pragma unroll 1
  for (int s = 0; s < 3; s++) {
    // ---- stage A (LDG -> swizzled STS), 64B per thread ----
    const __half* asec = g_Ahi + (size_t)s * NN * 64 + (size_t)node * 64 + ahalf * 32;
    uint4 av[4];
#pragma unroll
    for (int g = 0; g < 4; g++)
      av[g] = *reinterpret_cast<const uint4*>(asec + g * 8);
    if (s > 0) __syncthreads();  // previous compute done before overwrite
#pragma unroll
    for (int g = 0; g < 4; g++) {
      int kg = ahalf * 4 + g;
      *reinterpret_cast<uint4*>(smem + A_OFF + am * 128 +
                                ((kg ^ (am & 7)) << 4)) = av[g];
    }
    if (s == 0) { CP_WAIT(2); }
    else if (s == 1) { CP_WAIT(1); }
    else { CP_WAIT(0); }
    __syncthreads();

    uint32_t sBc = sB + s * 16384;
    // ---- compute: 4 k16-steps ----
#pragma unroll
    for (int ks = 0; ks < 4; ks++) {
      uint32_t a[4][4], bb[4][2];
#pragma unroll
      for (int mi = 0; mi < 4; mi++) {
        int arow = warpM * 64 + mi * 16 + ((matq & 1) << 3) + rq;
        int k8 = ks * 2 + (matq >> 1);
        ldsm_x4(a[mi], sA + arow * 128 + ((k8 ^ (arow & 7)) << 4));
      }
#pragma unroll
      for (int jp = 0; jp < 2; jp++) {
        int nrow = warpN * 32 + jp * 16 + ((matq >> 1) << 3) + rq;
        int k8 = ks * 2 + (matq & 1);
        uint32_t t4[4];
        ldsm_x4(t4, sBc + nrow * 128 + ((k8 ^ (nrow & 7)) << 4));
        bb[jp * 2][0] = t4[0]; bb[jp * 2][1] = t4[1];
        bb[jp * 2 + 1][0] = t4[2]; bb[jp * 2 + 1][1] = t4[3];
      }
#pragma unroll
      for (int mi = 0; mi < 4; mi++)
#pragma unroll
        for (int j = 0; j < 4; j++) mma_fp16(acc[mi][j], a[mi], bb[j]);
    }
  }
  __syncthreads();

  // ---- write accumulators to smem Y[128][130] fp32 ----
  float* Y = reinterpret_cast<float*>(smem);
  {
    int gid = lane >> 2, tig = lane & 3;
#pragma unroll
    for (int mi = 0; mi < 4; mi++) {
      int row = warpM * 64 + mi * 16 + gid;
#pragma unroll
      for (int j = 0; j < 4; j++) {
        int col = warpN * 32 + j * 8 + tig * 2;
        Y[row * 130 + col] = acc[mi][j][0];
        Y[row * 130 + col + 1] = acc[mi][j][1];
        Y[(row + 8) * 130 + col] = acc[mi][j][2];
        Y[(row + 8) * 130 + col + 1] = acc[mi][j][3];
      }
    }
  }
  __syncthreads();

  // ---- gates + head ----
  {
    int half = tid >> 7, m = tid & 127;
    int cb = half * 32;
    float d0 = 0.f, d1 = 0.f;
#pragma unroll
    for (int q = 0; q < 32; q++) {
      int dim = cb + q;
      float z = sigmoid_fast(Y[m * 130 + dim] + g_bcomb[dim]);
      float ht = tanh_fast(Y[m * 130 + 64 + dim] + g_bcomb[64 + dim]);
      float t = tanh_fast((1.0f - z) * ht);
      d0 += t * Wlin[dim * 2];
      d1 += t * Wlin[dim * 2 + 1];
    }
    float2* P = reinterpret_cast<float2*>(smem + P_OFF);
    if (half) P[m] = make_float2(d0, d1);
    __syncthreads();
    if (!half) {
      int onode = blockIdx.x * 128 + m;
      if (onode < NN) {
        float2 p = P[m];
        float v0 = d0 + p.x + blin[0];
        float v1 = d1 + p.y + blin[1];
        float o0 = 1.0f / (1.0f + __expf(-v0));
        float o1 = 1.0f / (1.0f + __expf(-v1));
        *(float2*)(out + onode * 2) = make_float2(o0, o1);
      }
    }
  }
}

// ---------------------------------------------------------------------------
extern "C" void kernel_launch(void* const* d_in, const int* in_sizes, int n_in,
                              void* d_out, int out_size) {
  const float* x    = (const float*)d_in[0];
  const int*   ei   = (const int*)d_in[1];
  const float* w    = (const float*)d_in[2];
  const float* Wxz  = (const float*)d_in[3];
  const float* bxz  = (const float*)d_in[4];
  const float* bhz  = (const float*)d_in[6];
  const float* Wxh  = (const float*)d_in[11];
  const float* bxh  = (const float*)d_in[12];
  const float* bhh  = (const float*)d_in[14];
  const float* Wlin = (const float*)d_in[15];
  const float* blin = (const float*)d_in[16];
  float* out = (float*)d_out;

  cudaFuncSetAttribute(k_gemm, cudaFuncAttributeMaxDynamicSharedMemorySize,
                       SMEM_GEMM);

  void* p_deg = nullptr;
  void* p_cnt = nullptr;
  cudaGetSymbolAddress(&p_deg, g_deg);
  cudaGetSymbolAddress(&p_cnt, g_cnt);
  cudaMemsetAsync(p_deg, 0, NN * sizeof(float));
  cudaMemsetAsync(p_cnt, 0, NN * sizeof(int));

  k_fused_init<<<EBLK + XBLK + WBLK + 1, 256>>>(x, ei, w, Wxz, Wxh, bxz, bhz,
                                                bxh, bhh);
  k_scan<<<1, 1024>>>();
  k_edge_fill<<<(EE + 255) / 256, 256>>>(ei, w);
  k_prop1<<<(NN * 32 + 255) / 256, 256>>>();
  k_prop2<<<(NN * 32 + 255) / 256, 256>>>(x);
  k_gemm<<<(NN + 127) / 128, 256, SMEM_GEMM>>>(Wlin, blin, out);
}